// round 2
// baseline (speedup 1.0000x reference)
#include <cuda_runtime.h>
#include <cstdint>

#define NCELL   81          // 9*9 map cells
#define MH      9
#define HW      16384       // 128*128 feature plane
#define BATCH   128
#define NTHREADS 512
#define V4      (HW / NTHREADS / 4)   // float4 chunks per thread = 8

// Reference constants: DECAY = float(np.exp(-0.01)); lr = f32(1.0*DECAY); radius = f32(5.0*DECAY)
#define LR_F     0.99004983374916811f
#define RADIUS_F 4.95024916874584055f

// persistent-kernel coordination state (global device memory; no allocation)
__device__ unsigned long long g_barcount;
__device__ unsigned long long g_minkey[2][NCELL];

__global__ void som_init_kernel() { g_barcount = 0ULL; }

__global__ __launch_bounds__(NTHREADS, 1)
void som_persistent_kernel(const float* __restrict__ x,
                           const float* __restrict__ w0,
                           float* __restrict__ out)
{
    extern __shared__ float wsh[];                // 16384 floats = 64 KB: this cell's W slice
    __shared__ float               s_sum[NTHREADS / 32];
    __shared__ unsigned long long  s_key[NTHREADS / 32];
    __shared__ float               s_g;

    const int cell = blockIdx.x;
    const int ci = cell / MH;
    const int cj = cell % MH;
    const int tid  = threadIdx.x;
    const int lane = tid & 31;
    const int warp = tid >> 5;

    // Load W0 slice into SMEM once; it persists (with in-place updates) across all steps.
    const float4* __restrict__ w0v = reinterpret_cast<const float4*>(w0 + (size_t)cell * HW);
    float4* wv = reinterpret_cast<float4*>(wsh);
    #pragma unroll
    for (int k = 0; k < V4; k++) wv[tid + k * NTHREADS] = w0v[tid + k * NTHREADS];
    __syncthreads();

    for (int t = 0; t < BATCH; t++) {
        const float4* __restrict__ xv = reinterpret_cast<const float4*>(x + (size_t)t * HW);

        // ---- per-thread partial: rings sum + (value, flat-index) lexicographic min ----
        float sum = 0.0f;
        float bestv = 3.402823466e+38f;
        int   bestp = 0;
        #pragma unroll
        for (int k = 0; k < V4; k++) {
            const int f4 = tid + k * NTHREADS;
            const float4 xq = xv[f4];
            const float4 wq = wv[f4];
            const float v0 = fabsf(wq.x - xq.x);
            const float v1 = fabsf(wq.y - xq.y);
            const float v2 = fabsf(wq.z - xq.z);
            const float v3 = fabsf(wq.w - xq.w);
            sum += v0 + v1 + v2 + v3;
            const int p = f4 * 4;
            // scanning order within thread is ascending p -> strict < keeps first occurrence
            if (v0 < bestv) { bestv = v0; bestp = p;     }
            if (v1 < bestv) { bestv = v1; bestp = p + 1; }
            if (v2 < bestv) { bestv = v2; bestp = p + 2; }
            if (v3 < bestv) { bestv = v3; bestp = p + 3; }
        }

        // pack (nonneg float bits, global flat index) -> u64; u64 min == lexicographic min
        unsigned long long key =
            ((unsigned long long)__float_as_uint(bestv) << 32) |
            (unsigned long long)(unsigned)(cell * HW + bestp);

        // ---- warp reduce ----
        #pragma unroll
        for (int o = 16; o > 0; o >>= 1) {
            sum += __shfl_down_sync(0xffffffffu, sum, o);
            unsigned long long k2 = __shfl_down_sync(0xffffffffu, key, o);
            key = (k2 < key) ? k2 : key;
        }
        if (lane == 0) { s_sum[warp] = sum; s_key[warp] = key; }
        __syncthreads();

        // ---- block finish + global barrier + neighborhood update scalar ----
        if (tid == 0) {
            float rings = s_sum[0];
            unsigned long long bk = s_key[0];
            #pragma unroll
            for (int wn = 1; wn < NTHREADS / 32; wn++) {
                rings += s_sum[wn];
                if (s_key[wn] < bk) bk = s_key[wn];
            }
            const int par = t & 1;
            g_minkey[par][cell] = bk;
            __threadfence();
            atomicAdd(&g_barcount, 1ULL);

            const unsigned long long target = (unsigned long long)(t + 1) * NCELL;
            while (*(volatile unsigned long long*)&g_barcount < target) __nanosleep(64);
            __threadfence();

            // global argmin across all 81 cells (u64 lexicographic min)
            unsigned long long gbest = g_minkey[par][0];
            #pragma unroll 4
            for (int c = 1; c < NCELL; c++) {
                const unsigned long long kk = g_minkey[par][c];
                if (kk < gbest) gbest = kk;
            }
            const int flat = (int)(unsigned)(gbest & 0xffffffffULL);
            const int wx = flat / MH;       // NB: reference divides by mh=9, not 9*128*128
            const int wy = flat % MH;

            const float dx = (float)(ci - wx);
            const float dy = (float)(cj - wy);
            const float dist = sqrtf(dx * dx + dy * dy);
            const float denom = 2.0f * (RADIUS_F * RADIUS_F);
            const float gauss = expf(-(dist * dist) / denom);
            float g = LR_F * gauss * rings;
            if (!(g < RADIUS_F)) g = 0.0f;   // jnp.where(g < radius, g, 0); NaN -> 0
            s_g = g;
        }
        __syncthreads();

        // ---- apply update (if any) and stream output tile ----
        const float g = s_g;
        float4* __restrict__ op =
            reinterpret_cast<float4*>(out + ((size_t)t * NCELL + cell) * HW);
        if (g != 0.0f) {
            #pragma unroll
            for (int k = 0; k < V4; k++) {
                const int f4 = tid + k * NTHREADS;
                float4 wq = wv[f4];
                wq.x += g; wq.y += g; wq.z += g; wq.w += g;
                wv[f4] = wq;        // each thread owns its slots; no cross-thread hazard
                op[f4] = wq;
            }
        } else {
            #pragma unroll
            for (int k = 0; k < V4; k++) {
                const int f4 = tid + k * NTHREADS;
                op[f4] = wv[f4];
            }
        }
        __syncthreads();
    }
}

extern "C" void kernel_launch(void* const* d_in, const int* in_sizes, int n_in,
                              void* d_out, int out_size)
{
    const float* x  = (const float*)d_in[0];
    const float* w0 = (const float*)d_in[1];
    // defensive: bind by element count (x = 128^3, weights = 9*9*128*128)
    if (n_in >= 2 && in_sizes[0] == NCELL * HW && in_sizes[1] == BATCH * HW) {
        w0 = (const float*)d_in[0];
        x  = (const float*)d_in[1];
    }

    cudaFuncSetAttribute(som_persistent_kernel,
                         cudaFuncAttributeMaxDynamicSharedMemorySize, HW * sizeof(float));

    som_init_kernel<<<1, 1>>>();
    som_persistent_kernel<<<NCELL, NTHREADS, HW * sizeof(float)>>>(x, w0, (float*)d_out);
}

// round 4
// speedup vs baseline: 2.0083x; 2.0083x over previous
#include <cuda_runtime.h>
#include <cstdint>

#define NCELL   81
#define MH      9
#define HW      16384        // 128*128
#define BATCH   128
#define NTA     512
#define V4      (HW / NTA / 4)   // 8 float4 per thread
#define NWARP   (NTA / 32)       // 16

#define LR_F     0.99004983374916811f
#define RADIUS_F 4.95024916874584055f
#define BIGF     3.402823466e+38f

__device__ unsigned long long g_barcount;
__device__ unsigned long long g_minkey[2][NCELL];
__device__ float              g_C[BATCH][NCELL];   // cumulative scalar update per (t, cell)

__global__ void som_init_kernel() { g_barcount = 0ULL; }

// ---------------------------------------------------------------------------
// Kernel A: sequential stats. One CTA per map cell (81 CTAs, all co-resident).
// W0 slice and current x_t live in SMEM; the per-step weight update is a
// uniform scalar per cell, carried as c (W_t = W0 + c). Emits only g_C.
// ---------------------------------------------------------------------------
__global__ __launch_bounds__(NTA, 1)
void som_stats_kernel(const float* __restrict__ x, const float* __restrict__ w0)
{
    extern __shared__ float sh[];        // [0,HW): w0 slice   [HW,2*HW): x_t
    float* wsh = sh;
    float* xsh = sh + HW;
    __shared__ float               s_sum[NWARP];
    __shared__ unsigned long long  s_key[NWARP];
    __shared__ float               s_g;

    const int cell = blockIdx.x;
    const int ci = cell / MH, cj = cell % MH;
    const int tid = threadIdx.x, lane = tid & 31, warp = tid >> 5;

    float4* wv = reinterpret_cast<float4*>(wsh);
    float4* xv = reinterpret_cast<float4*>(xsh);
    const float4* w0v = reinterpret_cast<const float4*>(w0 + (size_t)cell * HW);
    const float4* xg  = reinterpret_cast<const float4*>(x);

    #pragma unroll
    for (int k = 0; k < V4; k++) wv[tid + k * NTA] = w0v[tid + k * NTA];
    #pragma unroll
    for (int k = 0; k < V4; k++) xv[tid + k * NTA] = xg[tid + k * NTA];   // x_0
    __syncthreads();

    float c = 0.0f;   // cumulative scalar update for this cell

    for (int t = 0; t < BATCH; t++) {
        // ---- hot loop: sum of |w0 - x + c| and 4 independent min chains ----
        float sum0 = 0.0f, sum1 = 0.0f;
        float bv0 = BIGF, bv1 = BIGF, bv2 = BIGF, bv3 = BIGF;
        int   bp0 = 0,    bp1 = 0,    bp2 = 0,    bp3 = 0;
        #pragma unroll
        for (int k = 0; k < V4; k++) {
            const int f4 = tid + k * NTA;
            const float4 xq = xv[f4];
            const float4 wq = wv[f4];
            const float v0 = fabsf(wq.x - xq.x + c);
            const float v1 = fabsf(wq.y - xq.y + c);
            const float v2 = fabsf(wq.z - xq.z + c);
            const float v3 = fabsf(wq.w - xq.w + c);
            sum0 += v0 + v1;
            sum1 += v2 + v3;
            // strict < with ascending f4 keeps earliest index within each chain
            const bool m0 = v0 < bv0;  bp0 = m0 ? f4 : bp0;  bv0 = m0 ? v0 : bv0;
            const bool m1 = v1 < bv1;  bp1 = m1 ? f4 : bp1;  bv1 = m1 ? v1 : bv1;
            const bool m2 = v2 < bv2;  bp2 = m2 ? f4 : bp2;  bv2 = m2 ? v2 : bv2;
            const bool m3 = v3 < bv3;  bp3 = m3 ? f4 : bp3;  bv3 = m3 ? v3 : bv3;
        }
        float sum = sum0 + sum1;

        // combine the 4 chains via packed (valueBits, flatIdx) u64 keys;
        // u64 min == lexicographic (value, first-index) min for nonneg floats
        unsigned long long key;
        {
            const unsigned long long k0 = ((unsigned long long)__float_as_uint(bv0) << 32) | (unsigned)(cell * HW + bp0 * 4 + 0);
            const unsigned long long k1 = ((unsigned long long)__float_as_uint(bv1) << 32) | (unsigned)(cell * HW + bp1 * 4 + 1);
            const unsigned long long k2 = ((unsigned long long)__float_as_uint(bv2) << 32) | (unsigned)(cell * HW + bp2 * 4 + 2);
            const unsigned long long k3 = ((unsigned long long)__float_as_uint(bv3) << 32) | (unsigned)(cell * HW + bp3 * 4 + 3);
            const unsigned long long a = (k0 < k1) ? k0 : k1;
            const unsigned long long b = (k2 < k3) ? k2 : k3;
            key = (a < b) ? a : b;
        }

        // ---- warp reduce ----
        #pragma unroll
        for (int o = 16; o > 0; o >>= 1) {
            sum += __shfl_down_sync(0xffffffffu, sum, o);
            const unsigned long long k2 = __shfl_down_sync(0xffffffffu, key, o);
            key = (k2 < key) ? k2 : key;
        }
        if (lane == 0) { s_sum[warp] = sum; s_key[warp] = key; }
        __syncthreads();

        const int par = t & 1;

        if (warp == 0) {
            // block-level reduce of 16 warp partials, distributed over lanes
            float               rs = (lane < NWARP) ? s_sum[lane] : 0.0f;
            unsigned long long  rk = (lane < NWARP) ? s_key[lane] : ~0ULL;
            #pragma unroll
            for (int o = 16; o > 0; o >>= 1) {
                rs += __shfl_xor_sync(0xffffffffu, rs, o);
                const unsigned long long k2 = __shfl_xor_sync(0xffffffffu, rk, o);
                rk = (k2 < rk) ? k2 : rk;
            }
            // publish + arrive; ONLY lane 0 polls (backoff spin), then broadcast
            const unsigned long long target = (unsigned long long)(t + 1) * NCELL;
            if (lane == 0) {
                g_minkey[par][cell] = rk;
                __threadfence();
                atomicAdd(&g_barcount, 1ULL);
                while (*(volatile unsigned long long*)&g_barcount < target)
                    __nanosleep(32);
            }
            __syncwarp();
            __threadfence();

            // global argmin over 81 cells, distributed across 32 lanes
            unsigned long long gb = g_minkey[par][lane];
            {
                const unsigned long long a = g_minkey[par][lane + 32];
                if (a < gb) gb = a;
                if (lane + 64 < NCELL) {
                    const unsigned long long b = g_minkey[par][lane + 64];
                    if (b < gb) gb = b;
                }
            }
            #pragma unroll
            for (int o = 16; o > 0; o >>= 1) {
                const unsigned long long k2 = __shfl_xor_sync(0xffffffffu, gb, o);
                gb = (k2 < gb) ? k2 : gb;
            }

            if (lane == 0) {
                const int flat = (int)(unsigned)(gb & 0xffffffffULL);
                const int wx = flat / MH;      // reference divides flat by mh=9
                const int wy = flat % MH;
                const float dx = (float)(ci - wx);
                const float dy = (float)(cj - wy);
                const float dist = sqrtf(dx * dx + dy * dy);
                const float gauss = expf(-(dist * dist) / (2.0f * RADIUS_F * RADIUS_F));
                float g = LR_F * gauss * rs;
                if (!(g < RADIUS_F)) g = 0.0f;     // jnp.where(g < radius, g, 0)
                s_g = g;
                g_C[t][cell] = c + g;              // cumulative offset after this step
            }
        } else if (t + 1 < BATCH) {
            // warps 1..15 prefetch x_{t+1} into SMEM during the barrier window
            const float4* xn = reinterpret_cast<const float4*>(x + (size_t)(t + 1) * HW);
            for (int i = tid - 32; i < HW / 4; i += NTA - 32) xv[i] = xn[i];
        }
        __syncthreads();
        c += s_g;
        __syncthreads();   // protect s_g / s_sum / s_key from next-step overwrite
    }
}

// ---------------------------------------------------------------------------
// Kernel B: pure streaming.  out[t,cell,:] = w0[cell,:] + C[t,cell]
// ---------------------------------------------------------------------------
__global__ __launch_bounds__(NTA)
void som_out_kernel(const float* __restrict__ w0, float* __restrict__ out)
{
    const int b    = blockIdx.x;          // t*81 + cell
    const int t    = b / NCELL;
    const int cell = b - t * NCELL;
    const float c  = g_C[t][cell];

    const float4* __restrict__ wv = reinterpret_cast<const float4*>(w0 + (size_t)cell * HW);
    float4* __restrict__       ov = reinterpret_cast<float4*>(out + ((size_t)t * NCELL + cell) * HW);
    const int tid = threadIdx.x;
    #pragma unroll
    for (int k = 0; k < V4; k++) {
        float4 w = wv[tid + k * NTA];
        w.x += c; w.y += c; w.z += c; w.w += c;
        ov[tid + k * NTA] = w;
    }
}

extern "C" void kernel_launch(void* const* d_in, const int* in_sizes, int n_in,
                              void* d_out, int out_size)
{
    const float* x  = (const float*)d_in[0];
    const float* w0 = (const float*)d_in[1];
    if (n_in >= 2 && in_sizes[0] == NCELL * HW && in_sizes[1] == BATCH * HW) {
        w0 = (const float*)d_in[0];
        x  = (const float*)d_in[1];
    }

    cudaFuncSetAttribute(som_stats_kernel,
                         cudaFuncAttributeMaxDynamicSharedMemorySize, 2 * HW * sizeof(float));

    som_init_kernel<<<1, 1>>>();
    som_stats_kernel<<<NCELL, NTA, 2 * HW * sizeof(float)>>>(x, w0);
    som_out_kernel<<<BATCH * NCELL, NTA>>>(w0, (float*)d_out);
}